// round 4
// baseline (speedup 1.0000x reference)
#include <cuda_runtime.h>

#define NCLS 200
#define NP   10
#define D    512
#define D4   128        // D / 4 (16B granules)
#define NTOK 8192
#define ITERS 5
#define EPSF 0.01f
#define MAXC 128        // max tokens/class: binomial(8192,1/200) mean 41, sd 6.4 -> +13.6 sigma

// ---------------- device scratch (no allocations allowed) ----------------
__device__ int g_counts[NCLS];
__device__ int g_offsets[NCLS];
__device__ int g_tokidx[NTOK];
__device__ int g_is64;

typedef unsigned long long u64t;

__device__ __forceinline__ u64t pack2(float lo, float hi) {
    u64t r; asm("mov.b64 %0,{%1,%2};" : "=l"(r) : "f"(lo), "f"(hi)); return r;
}
__device__ __forceinline__ float2 unpack2(u64t v) {
    float2 f; asm("mov.b64 {%0,%1},%2;" : "=f"(f.x), "=f"(f.y) : "l"(v)); return f;
}
// d = a*b + d, lane-wise on packed f32x2 (FFMA2 — 2 FMAs per instruction)
__device__ __forceinline__ void fma2(u64t& d, u64t a, u64t b) {
    asm("fma.rn.f32x2 %0,%1,%2,%0;" : "+l"(d) : "l"(a), "l"(b));
}
__device__ __forceinline__ float warpsum(float x) {
    #pragma unroll
    for (int o = 16; o; o >>= 1) x += __shfl_xor_sync(0xffffffff, x, o);
    return x;
}
__device__ __forceinline__ float hsum2(u64t v) { float2 f = unpack2(v); return f.x + f.y; }
__device__ __forceinline__ float dot4(float4 a, float4 b) {
    return a.x * b.x + a.y * b.y + a.z * b.z + a.w * b.w;
}

// ---------------- k1: fused probe + histogram + scan + scatter (1 block) ----------------
__global__ void __launch_bounds__(1024) k_prep(const int* __restrict__ labels) {
    __shared__ int scnt[NCLS];     // histogram, then cursors
    __shared__ int ssum[256];      // inclusive scan
    __shared__ int s_is64;
    int t = threadIdx.x;
    if (t == 0) {
        // int64 LE labels in [0,200): every odd 32-bit word of the first 32
        // entries is 0 and every even word in range. For genuine int32 labels
        // the odds of that are ~(1/200)^32 — safe probe.
        int is64 = 1;
        for (int i = 0; i < 32; i++) {
            int lo = labels[2 * i], hi = labels[2 * i + 1];
            if (hi != 0 || lo < 0 || lo >= NCLS) { is64 = 0; break; }
        }
        s_is64 = is64;
        g_is64 = is64;
    }
    for (int i = t; i < NCLS; i += 1024) scnt[i] = 0;
    __syncthreads();
    int is64 = s_is64;
    int lab[8];
    #pragma unroll
    for (int k = 0; k < 8; k++) {
        int n = t + 1024 * k;
        lab[k] = is64 ? labels[2 * n] : labels[n];
        atomicAdd(&scnt[lab[k]], 1);
    }
    __syncthreads();
    int v = 0;
    if (t < 256) { v = (t < NCLS) ? scnt[t] : 0; ssum[t] = v; }
    __syncthreads();
    #pragma unroll
    for (int o = 1; o < 256; o <<= 1) {
        int add = 0;
        if (t < 256 && t >= o) add = ssum[t - o];
        __syncthreads();
        if (t < 256) ssum[t] += add;
        __syncthreads();
    }
    if (t < NCLS) {
        g_counts[t] = v;
        int off = ssum[t] - v;      // exclusive
        g_offsets[t] = off;
        scnt[t] = off;              // reuse as cursor
    }
    __syncthreads();
    #pragma unroll
    for (int k = 0; k < 8; k++) {
        int pos = atomicAdd(&scnt[lab[k]], 1);
        g_tokidx[pos] = t + 1024 * k;   // order within class nondeterministic -> sorted in k_class
    }
}

// ---------------- k2: fused per-class norm + scores + Sinkhorn + update ----------------
__global__ void __launch_bounds__(320, 2)
k_class(const float* __restrict__ tokens,
        const float* __restrict__ protos,
        float* __restrict__ out) {
    __shared__ float4 psh4[NP * D4];     // 20KB: protos for S-pass; aliased as partial buf later
    __shared__ float  Ssh[MAXC * NP];    // scores -> final fused weights
    __shared__ float  vsh[MAXC];
    __shared__ float  insh[MAXC];
    __shared__ int    jsh[MAXC];
    __shared__ int    js2[MAXC];
    __shared__ float  ush[NP];
    __shared__ float  red[4 * NP];
    __shared__ float  invp[NP];

    int c = blockIdx.x;
    int t = threadIdx.x, w = t >> 5, lane = t & 31;
    int nc = g_counts[c];
    if (nc > MAXC) nc = MAXC;            // unreachable safety clamp
    int base = g_offsets[c];

    // stage this class's 10 prototype rows into smem
    const float4* Pg = (const float4*)protos + (size_t)c * NP * D4;
    for (int i = t; i < NP * D4; i += 320) psh4[i] = Pg[i];

    for (int j = t; j < nc; j += 320) { jsh[j] = g_tokidx[base + j]; vsh[j] = 0.f; }
    if (t < NP) ush[t] = 0.f;
    __syncthreads();

    // parallel rank sort (keys unique) — deterministic token order
    if (t < nc) {
        int key = jsh[t], r = 0;
        for (int a = 0; a < nc; a++) r += (jsh[a] < key);
        js2[r] = key;
    }
    __syncthreads();
    if (t < nc) jsh[t] = js2[t];
    __syncthreads();

    // ---- S-pass: warp per token pair; protos from smem, tokens from gmem; FFMA2 ----
    const ulonglong2* ps2 = (const ulonglong2*)psh4;
    for (int j0 = 2 * w; j0 < nc; j0 += 2 * NP) {
        int jA = jsh[j0];
        int hasB = (j0 + 1) < nc;
        int jB = hasB ? jsh[j0 + 1] : jA;
        const ulonglong2* TA = (const ulonglong2*)(tokens + (size_t)jA * D);
        const ulonglong2* TB = (const ulonglong2*)(tokens + (size_t)jB * D);
        ulonglong2 ta[4], tb[4];
        #pragma unroll
        for (int q = 0; q < 4; q++) { ta[q] = TA[lane + 32 * q]; tb[q] = TB[lane + 32 * q]; }
        u64t na2 = 0ull, nb2 = 0ull;
        #pragma unroll
        for (int q = 0; q < 4; q++) {
            fma2(na2, ta[q].x, ta[q].x); fma2(na2, ta[q].y, ta[q].y);
            fma2(nb2, tb[q].x, tb[q].x); fma2(nb2, tb[q].y, tb[q].y);
        }
        u64t accA[NP], accB[NP];
        #pragma unroll
        for (int p = 0; p < NP; p++) { accA[p] = 0ull; accB[p] = 0ull; }
        #pragma unroll
        for (int p = 0; p < NP; p++) {
            #pragma unroll
            for (int q = 0; q < 4; q++) {
                ulonglong2 pv = ps2[p * D4 + lane + 32 * q];
                fma2(accA[p], pv.x, ta[q].x);
                fma2(accA[p], pv.y, ta[q].y);
                fma2(accB[p], pv.x, tb[q].x);
                fma2(accB[p], pv.y, tb[q].y);
            }
        }
        float na = warpsum(hsum2(na2));
        float nb = warpsum(hsum2(nb2));
        float sA[NP], sB[NP];
        #pragma unroll
        for (int p = 0; p < NP; p++) { sA[p] = warpsum(hsum2(accA[p])); sB[p] = warpsum(hsum2(accB[p])); }
        if (lane == 0) {
            float ia = rsqrtf(na) * sqrtf(na) / na;  // avoid fast-math surprises: plain 1/sqrt
            ia = 1.f / sqrtf(na);
            insh[j0] = ia;
            #pragma unroll
            for (int p = 0; p < NP; p++) Ssh[j0 * NP + p] = sA[p] * ia;
            if (hasB) {
                float ib = 1.f / sqrtf(nb);
                insh[j0 + 1] = ib;
                #pragma unroll
                for (int p = 0; p < NP; p++) Ssh[(j0 + 1) * NP + p] = sB[p] * ib;
            }
        }
    }
    __syncthreads();

    // ---- Sinkhorn (log-domain, matches reference u-then-v order) ----
    if (nc > 0) {
        const float invE = 1.0f / EPSF;
        const float log_a = logf(1.0f / (float)NP + 1e-8f);
        const float log_b = logf(1.0f / (float)nc + 1e-8f);
        for (int it = 0; it < ITERS; it++) {
            // u update: warp w owns prototype row w (10 warps = NP)
            float uold = ush[w];
            float m = -1e30f, s = 0.f;
            for (int j = lane; j < nc; j += 32)
                m = fmaxf(m, Ssh[j * NP + w] + uold + vsh[j]);
            #pragma unroll
            for (int o = 16; o; o >>= 1) m = fmaxf(m, __shfl_xor_sync(0xffffffff, m, o));
            for (int j = lane; j < nc; j += 32)
                s += expf((Ssh[j * NP + w] + uold + vsh[j] - m) * invE);
            s = warpsum(s);
            if (lane == 0) ush[w] = EPSF * (log_a - (m * invE + logf(s))) + uold;
            __syncthreads();
            // v update (new u, old v): one thread per column
            for (int j = t; j < nc; j += 320) {
                float vold = vsh[j];
                float m2 = -1e30f;
                #pragma unroll
                for (int p = 0; p < NP; p++)
                    m2 = fmaxf(m2, Ssh[j * NP + p] + ush[p] + vold);
                float s2 = 0.f;
                #pragma unroll
                for (int p = 0; p < NP; p++)
                    s2 += expf((Ssh[j * NP + p] + ush[p] + vold - m2) * invE);
                vsh[j] = EPSF * (log_b - (m2 * invE + logf(s2))) + vold;
            }
            __syncthreads();
        }
        // final plan, column-normalized, folded with token inv-norm
        for (int j = t; j < nc; j += 320) {
            float vj = vsh[j];
            float pi[NP], cs = 0.f;
            #pragma unroll
            for (int p = 0; p < NP; p++) {
                float e = expf((Ssh[j * NP + p] + ush[p] + vj) * invE);
                pi[p] = e; cs += e;
            }
            float f = insh[j] / cs;          // (pi/colsum) * inv_norm(token j)
            #pragma unroll
            for (int p = 0; p < NP; p++) Ssh[j * NP + p] = pi[p] * f;
        }
    }
    __syncthreads();

    // ---- update: thread-per-16B-dim, 2 token groups, FFMA2 accumulators ----
    int g = t >> 7;          // group 0: t<128, group 1: 128..255, warps 8-9 idle
    int tid = t & 127;
    u64t acc01[NP], acc23[NP];
    #pragma unroll
    for (int p = 0; p < NP; p++) { acc01[p] = 0ull; acc23[p] = 0ull; }
    if (t < 256) {
        for (int jj = g; jj < nc; jj += 2) {
            const ulonglong2* T = (const ulonglong2*)(tokens + (size_t)jsh[jj] * D);
            ulonglong2 tv = T[tid];
            #pragma unroll
            for (int p = 0; p < NP; p++) {
                float wgt = Ssh[jj * NP + p];
                u64t w2 = pack2(wgt, wgt);
                fma2(acc01[p], w2, tv.x);
                fma2(acc23[p], w2, tv.y);
            }
        }
    }
    __syncthreads();   // S-pass psh4 dead; Ssh reads done
    ulonglong2* part2 = (ulonglong2*)psh4;   // alias 20KB proto buffer as partial store
    if (g == 1 && t < 256) {
        #pragma unroll
        for (int p = 0; p < NP; p++) {
            ulonglong2 v; v.x = acc01[p]; v.y = acc23[p];
            part2[p * D4 + tid] = v;
        }
    }
    __syncthreads();
    if (g == 0) {
        float ssq[NP];
        float4 z[NP];
        #pragma unroll
        for (int p = 0; p < NP; p++) {
            ulonglong2 ov = part2[p * D4 + tid];
            float2 a01 = unpack2(acc01[p]), a23 = unpack2(acc23[p]);
            float2 o01 = unpack2(ov.x),     o23 = unpack2(ov.y);
            float4 pv = Pg[p * D4 + tid];            // protos from L2 (warm)
            float4 zz;
            zz.x = 0.98f * pv.x + 0.02f * (a01.x + o01.x);
            zz.y = 0.98f * pv.y + 0.02f * (a01.y + o01.y);
            zz.z = 0.98f * pv.z + 0.02f * (a23.x + o23.x);
            zz.w = 0.98f * pv.w + 0.02f * (a23.y + o23.y);
            z[p] = zz;
            ssq[p] = dot4(zz, zz);
        }
        #pragma unroll
        for (int p = 0; p < NP; p++) {
            float s = warpsum(ssq[p]);
            if (lane == 0) red[w * NP + p] = s;      // w in 0..3 here
        }
        __syncthreads();
        if (t < NP) {
            float s = red[t] + red[NP + t] + red[2 * NP + t] + red[3 * NP + t];
            invp[t] = 1.f / sqrtf(s);
        }
        __syncthreads();
        float4* O = (float4*)out + (size_t)c * NP * D4;
        #pragma unroll
        for (int p = 0; p < NP; p++) {
            float iv = invp[p];
            float4 zz = z[p];
            zz.x *= iv; zz.y *= iv; zz.z *= iv; zz.w *= iv;
            O[p * D4 + tid] = zz;
        }
    } else {
        __syncthreads();    // match group-0 barriers
        __syncthreads();
    }
}

// ---------------- launch ----------------
extern "C" void kernel_launch(void* const* d_in, const int* in_sizes, int n_in,
                              void* d_out, int out_size) {
    const float* tokens = (const float*)d_in[0];
    const int*   labels = (const int*)d_in[1];   // int32 or int64, probed on device
    const float* protos = (const float*)d_in[2];
    float* out = (float*)d_out;

    k_prep<<<1, 1024>>>(labels);
    k_class<<<NCLS, 320>>>(tokens, protos, out);
}